// round 15
// baseline (speedup 1.0000x reference)
#include <cuda_runtime.h>

// ============================================================================
// QFCModel: 4-qubit / 3-layer variational circuit + Linear(4,4) + BatchNorm1d
//
//   out_j(sample) = sum_{k in {0,1,2}^4} C_j[k] * prod_i b_i[k_i],
//   b_i = (1, cos t_i, sin t_i),  t_i = 2*pi*(x_i - mn)*inv_range
//
// 3-node graph: precompute(1 blk) -> memcpyToSymbol -> fused persistent kernel.
// R14 post-mortem: +70% warps raised issue only 21->26% and duration was flat
// -> per-warp dependency latency binds (streaming chain is deep, only 4
// independent j-chains; FFMA2 rt~3 from RF banking).
// R15: DUAL-CHAIN streaming — 4 samples/thread as two f32x2 chains sharing
// every coefficient load (LDS.128 + LDC each feed both chains). Doubles
// per-warp ILP and halves load issues per sample while streaming order keeps
// live regs ~105 -> 2 blocks/SM at 256 thr. NBLK=296 (=2x148, all resident).
// ============================================================================

typedef unsigned long long u64;

#define NBLK 296
#define NTHR 256
#define SPT  8          // 296*256*8 = 606208 >= 524288 (guards handle tail)

static __constant__ u64 c_Cb[108];    // base terms [4][27], lane-duplicated

__device__ u64        g_Cb[108];      // staging for c_Cb
__device__ ulonglong2 g_Cp[4][27];    // (cos,sin) coeff pairs, lane-duplicated
__device__ unsigned   g_umin = 0xFFFFFFFFu;
__device__ unsigned   g_umax = 0u;
__device__ unsigned   g_bar0 = 0u, g_bar1 = 0u;
__device__ double     g_accd[8] = {0,0,0,0,0,0,0,0};   // sum[4], sumsq[4]

__device__ __forceinline__ u64 pk2(float lo, float hi) {
    u64 r; asm("mov.b64 %0, {%1, %2};" : "=l"(r) : "f"(lo), "f"(hi)); return r;
}
__device__ __forceinline__ void upk2(float& lo, float& hi, u64 v) {
    asm("mov.b64 {%0, %1}, %2;" : "=f"(lo), "=f"(hi) : "l"(v));
}
__device__ __forceinline__ u64 fma2(u64 a, u64 b, u64 c) {
    u64 d; asm("fma.rn.f32x2 %0, %1, %2, %3;" : "=l"(d) : "l"(a), "l"(b), "l"(c));
    return d;
}
// order-preserving float <-> uint (for integer atomic min/max)
__device__ __forceinline__ unsigned fenc(float f) {
    unsigned u = __float_as_uint(f);
    return (u & 0x80000000u) ? ~u : (u | 0x80000000u);
}
__device__ __forceinline__ float fdec(unsigned u) {
    return (u & 0x80000000u) ? __uint_as_float(u & 0x7FFFFFFFu)
                             : __uint_as_float(~u);
}
// software grid barrier: atomic arrive; ld.cg poll with a bounded fallback
__device__ __forceinline__ void grid_barrier(unsigned* ctr) {
    __syncthreads();
    if (threadIdx.x == 0) {
        __threadfence();
        unsigned arrived = atomicAdd(ctr, 1u) + 1u;
        if (arrived < gridDim.x) {
            int spins = 0;
            for (;;) {
                unsigned v;
                asm volatile("ld.global.cg.u32 %0, [%1];" : "=r"(v) : "l"(ctr));
                if (v >= gridDim.x) break;
                if (++spins >= 1024) {      // fallback path: force L2 read
                    if (atomicAdd(ctr, 0u) >= gridDim.x) break;
                    spins = 0;
                }
                __nanosleep(32);
            }
        }
        __threadfence();
    }
    __syncthreads();
}

// ---------------------------------------------------------------------------
// Node 1 (1 block, 128 threads): probe-grid coefficient construction + reset
// of all per-replay device state. Thread t < 81 simulates the circuit at
// probe point with base-3 digits of t (wire 0 most significant, stride 27),
// t_i = {0, pi/2, pi}[digit]. Amplitude bit (3-i) = wire i.
// ---------------------------------------------------------------------------
__global__ void __launch_bounds__(128) k_precompute(const float* __restrict__ w,
                                                    const float* __restrict__ fcw,
                                                    const float* __restrict__ fcb) {
    __shared__ float E[4][81];
    __shared__ float F[4][81];
    __shared__ float tc[24], ts[24];
    __shared__ float sfw[16], sfb[4];

    int t = threadIdx.x;
    if (t == 127) {            // per-replay resets (run before the fused kernel)
        g_umin = 0xFFFFFFFFu;
        g_umax = 0u;
        g_bar0 = 0u;
        g_bar1 = 0u;
        #pragma unroll
        for (int j = 0; j < 8; ++j) g_accd[j] = 0.0;
    }
    if (t < 24) { float a = 0.5f * w[t]; tc[t] = cosf(a); ts[t] = sinf(a); }
    if (t < 16) sfw[t] = fcw[t];
    if (t < 4)  sfb[t] = fcb[t];
    __syncthreads();

    if (t < 81) {
        int gd[4];
        gd[0] = t / 27; gd[1] = (t / 9) % 3; gd[2] = (t / 3) % 3; gd[3] = t % 3;
        const float encc[3] = {1.0f, 0.70710678118654752f, 0.0f};
        const float encs[3] = {0.0f, 0.70710678118654752f, 1.0f};

        float ar[16], ai[16];
        #pragma unroll
        for (int a = 0; a < 16; ++a) { ar[a] = 0.0f; ai[a] = 0.0f; }
        ar[0] = 1.0f;

        // input-encoding RYs
        #pragma unroll
        for (int i = 0; i < 4; ++i) {
            int m = 8 >> i;
            float c = encc[gd[i]], s = encs[gd[i]];
            #pragma unroll
            for (int a = 0; a < 16; ++a) {
                if (a & m) continue;
                float x0r = ar[a],     x0i = ai[a];
                float x1r = ar[a | m], x1i = ai[a | m];
                ar[a]     = c * x0r - s * x1r;  ai[a]     = c * x0i - s * x1i;
                ar[a | m] = s * x0r + c * x1r;  ai[a | m] = s * x0i + c * x1i;
            }
        }
        // ansatz layers
        for (int l = 0; l < 3; ++l) {
            #pragma unroll
            for (int i = 0; i < 4; ++i) {
                int m = 8 >> i;
                int base = (l * 4 + i) * 2;
                float cy = tc[base], sy = ts[base];
                float cz = tc[base + 1], sz = ts[base + 1];
                #pragma unroll
                for (int a = 0; a < 16; ++a) {
                    if (a & m) continue;
                    float x0r = ar[a],     x0i = ai[a];
                    float x1r = ar[a | m], x1i = ai[a | m];
                    float n0r = cy * x0r - sy * x1r, n0i = cy * x0i - sy * x1i;
                    float n1r = sy * x0r + cy * x1r, n1i = sy * x0i + cy * x1i;
                    // RZ: bit0 phase (cz - i sz), bit1 phase (cz + i sz)
                    ar[a]     = cz * n0r + sz * n0i;  ai[a]     = cz * n0i - sz * n0r;
                    ar[a | m] = cz * n1r - sz * n1i;  ai[a | m] = cz * n1i + sz * n1r;
                }
            }
            // CNOT chain (0,1)(1,2)(2,3)(3,0)
            #pragma unroll
            for (int e = 0; e < 4; ++e) {
                int cwire = e, twire = (e + 1) & 3;
                int mc = 8 >> cwire, mt = 8 >> twire;
                #pragma unroll
                for (int a = 0; a < 16; ++a) {
                    if ((a & mc) && !(a & mt)) {
                        int b = a ^ mt;
                        float vr = ar[a], vi = ai[a];
                        ar[a] = ar[b]; ai[a] = ai[b];
                        ar[b] = vr;    ai[b] = vi;
                    }
                }
            }
        }
        // PauliZ expvals
        float z[4] = {0.f, 0.f, 0.f, 0.f};
        #pragma unroll
        for (int a = 0; a < 16; ++a) {
            float p = ar[a] * ar[a] + ai[a] * ai[a];
            #pragma unroll
            for (int i = 0; i < 4; ++i)
                z[i] += (a & (8 >> i)) ? -p : p;
        }
        #pragma unroll
        for (int j = 0; j < 4; ++j) {
            float o = sfb[j];
            #pragma unroll
            for (int i = 0; i < 4; ++i) o += sfw[j * 4 + i] * z[i];
            E[j][t] = o;
        }
    }
    __syncthreads();

    // Per-mode inverse transforms: f(0),f(pi/2),f(pi) -> (1,cos,sin) coeffs
    {
        float (*S)[81] = E; float (*D)[81] = F;
        const int strides[4] = {27, 9, 3, 1};
        #pragma unroll
        for (int mode = 0; mode < 4; ++mode) {
            int st = strides[mode];
            for (int idx = t; idx < 324; idx += 128) {
                int j = idx / 81, g = idx - (idx / 81) * 81;
                int dg = (g / st) % 3;
                if (dg == 0) {
                    float f0 = S[j][g], f1 = S[j][g + st], f2 = S[j][g + 2 * st];
                    float A = 0.5f * (f0 + f2);
                    D[j][g]          = A;                 // const
                    D[j][g + st]     = 0.5f * (f0 - f2);  // cos coeff
                    D[j][g + 2 * st] = f1 - A;            // sin coeff
                }
            }
            __syncthreads();
            float (*tmp)[81] = S; S = D; D = tmp;
        }
        // after 4 swaps result is in E. Emit split layout for the hot loop:
        // triple m = 9a+3b covers flat indices {3m, 3m+1, 3m+2} =
        // {base (digit3=0), cos (digit3=1), sin (digit3=2)}.
        for (int idx = t; idx < 108; idx += 128) {
            int j = idx / 27, m = idx - (idx / 27) * 27;
            float b  = E[j][3 * m];
            float cc = E[j][3 * m + 1];
            float ss = E[j][3 * m + 2];
            g_Cb[idx]   = pk2(b, b);
            g_Cp[j][m]  = make_ulonglong2(pk2(cc, cc), pk2(ss, ss));
        }
    }
}

// ---------------------------------------------------------------------------
// Node 3: persistent fused kernel.
//   Phase 1: minmax over 8 samples/thread -> global encoded atomics
//   barrier -> Phase 2: 2 groups x 4 samples (two f32x2 chains sharing every
//   coefficient load; streaming wire-3-first order) -> RED.F64 BN stats ->
//   barrier -> Phase 3: BN apply on L2-resident outputs.
// ---------------------------------------------------------------------------
__global__ void __launch_bounds__(NTHR, 2) k_fused(const float4* __restrict__ x4,
                                                   float4* __restrict__ out, int B,
                                                   const float* __restrict__ gamma,
                                                   const float* __restrict__ beta) {
    __shared__ ulonglong2 sCp[4][27];       // (cos,sin) coeff pairs, 16B aligned
    __shared__ unsigned srmn[8], srmx[8];
    __shared__ float red[8][8];
    __shared__ float4 sbn[2];               // [0]=scale, [1]=shift

    int tid = threadIdx.x;
    const size_t STRIDE = (size_t)NBLK * NTHR;
    size_t gtid = (size_t)blockIdx.x * NTHR + tid;

    // stage (cos,sin) coefficient pairs into shared
    for (int i = tid; i < 108; i += NTHR) {
        int j = i / 27, m = i - (i / 27) * 27;
        sCp[j][m] = g_Cp[j][m];
    }

    // ---- Phase 1: min/max ----
    float mn = 3.402823e38f, mx = -3.402823e38f;
    #pragma unroll
    for (int q = 0; q < SPT; ++q) {
        size_t s = gtid + (size_t)q * STRIDE;
        if (s < (size_t)B) {
            float4 v = __ldg(x4 + s * 4);   // row stride = 16 floats
            mn = fminf(mn, fminf(fminf(v.x, v.y), fminf(v.z, v.w)));
            mx = fmaxf(mx, fmaxf(fmaxf(v.x, v.y), fmaxf(v.z, v.w)));
        }
    }
    unsigned emn = __reduce_min_sync(0xffffffffu, fenc(mn));
    unsigned emx = __reduce_max_sync(0xffffffffu, fenc(mx));
    int w = tid >> 5;
    if ((tid & 31) == 0) { srmn[w] = emn; srmx[w] = emx; }
    __syncthreads();
    if (tid == 0) {
        unsigned a = srmn[0], b = srmx[0];
        #pragma unroll
        for (int i = 1; i < 8; ++i) { a = min(a, srmn[i]); b = max(b, srmx[i]); }
        atomicMin(&g_umin, a);
        atomicMax(&g_umax, b);
    }

    grid_barrier(&g_bar0);

    // ---- Phase 2: contraction + BN stats ----
    unsigned uamn, uamx;
    asm volatile("ld.global.cg.u32 %0, [%1];" : "=r"(uamn) : "l"(&g_umin));
    asm volatile("ld.global.cg.u32 %0, [%1];" : "=r"(uamx) : "l"(&g_umax));
    float mnv = fdec(uamn);
    float scl = 6.283185307179586f / (fdec(uamx) - mnv + 1e-8f);

    float p[8];
    #pragma unroll
    for (int j = 0; j < 8; ++j) p[j] = 0.f;

    #pragma unroll 1
    for (int g = 0; g < SPT / 4; ++g) {
        size_t s0 = gtid + (size_t)(4 * g) * STRIDE;     // chain A: s0, s1
        size_t s1 = s0 + STRIDE;
        size_t s2 = s0 + 2 * STRIDE;                     // chain B: s2, s3
        size_t s3 = s0 + 3 * STRIDE;
        float4 z4 = make_float4(0.f, 0.f, 0.f, 0.f);
        float4 v0 = (s0 < (size_t)B) ? __ldg(x4 + s0 * 4) : z4;
        float4 v1 = (s1 < (size_t)B) ? __ldg(x4 + s1 * 4) : z4;
        float4 v2 = (s2 < (size_t)B) ? __ldg(x4 + s2 * 4) : z4;
        float4 v3f = (s3 < (size_t)B) ? __ldg(x4 + s3 * 4) : z4;

        float c0[4], sn0[4], c1[4], sn1[4], c2[4], sn2[4], c3[4], sn3[4];
        __sincosf((v0.x - mnv) * scl, &sn0[0], &c0[0]);
        __sincosf((v0.y - mnv) * scl, &sn1[0], &c1[0]);
        __sincosf((v0.z - mnv) * scl, &sn2[0], &c2[0]);
        __sincosf((v0.w - mnv) * scl, &sn3[0], &c3[0]);
        __sincosf((v1.x - mnv) * scl, &sn0[1], &c0[1]);
        __sincosf((v1.y - mnv) * scl, &sn1[1], &c1[1]);
        __sincosf((v1.z - mnv) * scl, &sn2[1], &c2[1]);
        __sincosf((v1.w - mnv) * scl, &sn3[1], &c3[1]);
        __sincosf((v2.x - mnv) * scl, &sn0[2], &c0[2]);
        __sincosf((v2.y - mnv) * scl, &sn1[2], &c1[2]);
        __sincosf((v2.z - mnv) * scl, &sn2[2], &c2[2]);
        __sincosf((v2.w - mnv) * scl, &sn3[2], &c3[2]);
        __sincosf((v3f.x - mnv) * scl, &sn0[3], &c0[3]);
        __sincosf((v3f.y - mnv) * scl, &sn1[3], &c1[3]);
        __sincosf((v3f.z - mnv) * scl, &sn2[3], &c2[3]);
        __sincosf((v3f.w - mnv) * scl, &sn3[3], &c3[3]);

        u64 CA0 = pk2(c0[0], c0[1]), SA0 = pk2(sn0[0], sn0[1]);
        u64 CA1 = pk2(c1[0], c1[1]), SA1 = pk2(sn1[0], sn1[1]);
        u64 CA2 = pk2(c2[0], c2[1]), SA2 = pk2(sn2[0], sn2[1]);
        u64 CA3 = pk2(c3[0], c3[1]), SA3 = pk2(sn3[0], sn3[1]);
        u64 CB0 = pk2(c0[2], c0[3]), SB0 = pk2(sn0[2], sn0[3]);
        u64 CB1 = pk2(c1[2], c1[3]), SB1 = pk2(sn1[2], sn1[3]);
        u64 CB2 = pk2(c2[2], c2[3]), SB2 = pk2(sn2[2], sn2[3]);
        u64 CB3 = pk2(c3[2], c3[3]), SB3 = pk2(sn3[2], sn3[3]);

        u64 oA[4], oB[4];
        #pragma unroll
        for (int j = 0; j < 4; ++j) {
            u64 vA[3], vB[3];
            #pragma unroll
            for (int a = 0; a < 3; ++a) {
                u64 uA[3], uB[3];
                #pragma unroll
                for (int b = 0; b < 3; ++b) {
                    int m = 9 * a + 3 * b;
                    ulonglong2 p0 = sCp[j][m];           // shared by both chains
                    ulonglong2 p1 = sCp[j][m + 1];
                    ulonglong2 p2 = sCp[j][m + 2];
                    u64 cb0 = c_Cb[j * 27 + m];
                    u64 cb1 = c_Cb[j * 27 + m + 1];
                    u64 cb2 = c_Cb[j * 27 + m + 2];
                    u64 tA0 = fma2(CA3, p0.x, fma2(SA3, p0.y, cb0));
                    u64 tB0 = fma2(CB3, p0.x, fma2(SB3, p0.y, cb0));
                    u64 tA1 = fma2(CA3, p1.x, fma2(SA3, p1.y, cb1));
                    u64 tB1 = fma2(CB3, p1.x, fma2(SB3, p1.y, cb1));
                    u64 tA2 = fma2(CA3, p2.x, fma2(SA3, p2.y, cb2));
                    u64 tB2 = fma2(CB3, p2.x, fma2(SB3, p2.y, cb2));
                    uA[b] = fma2(CA2, tA1, fma2(SA2, tA2, tA0));
                    uB[b] = fma2(CB2, tB1, fma2(SB2, tB2, tB0));
                }
                vA[a] = fma2(CA1, uA[1], fma2(SA1, uA[2], uA[0]));
                vB[a] = fma2(CB1, uB[1], fma2(SB1, uB[2], uB[0]));
            }
            oA[j] = fma2(CA0, vA[1], fma2(SA0, vA[2], vA[0]));
            oB[j] = fma2(CB0, vB[1], fma2(SB0, vB[2], vB[0]));
        }

        float o0[4], o1[4], o2[4], o3[4];
        #pragma unroll
        for (int j = 0; j < 4; ++j) {
            upk2(o0[j], o1[j], oA[j]);
            upk2(o2[j], o3[j], oB[j]);
        }
        if (s0 < (size_t)B) out[s0] = make_float4(o0[0], o0[1], o0[2], o0[3]);
        if (s1 < (size_t)B) out[s1] = make_float4(o1[0], o1[1], o1[2], o1[3]);
        if (s2 < (size_t)B) out[s2] = make_float4(o2[0], o2[1], o2[2], o2[3]);
        if (s3 < (size_t)B) out[s3] = make_float4(o3[0], o3[1], o3[2], o3[3]);

        #pragma unroll
        for (int j = 0; j < 4; ++j) {
            float a0 = (s0 < (size_t)B) ? o0[j] : 0.f;
            float a1 = (s1 < (size_t)B) ? o1[j] : 0.f;
            float a2 = (s2 < (size_t)B) ? o2[j] : 0.f;
            float a3 = (s3 < (size_t)B) ? o3[j] : 0.f;
            p[j]     += (a0 + a1) + (a2 + a3);
            p[4 + j] += (a0 * a0 + a1 * a1) + (a2 * a2 + a3 * a3);
        }
    }

    #pragma unroll
    for (int o2 = 16; o2 > 0; o2 >>= 1) {
        #pragma unroll
        for (int j = 0; j < 8; ++j)
            p[j] += __shfl_xor_sync(0xffffffffu, p[j], o2);
    }
    if ((tid & 31) == 0) {
        #pragma unroll
        for (int j = 0; j < 8; ++j) red[w][j] = p[j];
    }
    __syncthreads();
    if (tid < 8) {
        float a = 0.f;
        #pragma unroll
        for (int i = 0; i < 8; ++i) a += red[i][tid];
        atomicAdd(&g_accd[tid], (double)a);
    }

    grid_barrier(&g_bar1);

    // ---- Phase 3: BN params + apply ----
    if (tid == 0) {
        double s[8];
        #pragma unroll
        for (int j = 0; j < 8; ++j) {
            double v;
            asm volatile("ld.global.cg.f64 %0, [%1];" : "=d"(v) : "l"(&g_accd[j]));
            s[j] = v;
        }
        double invB = 1.0 / (double)B;
        float scv[4], shv[4];
        #pragma unroll
        for (int j = 0; j < 4; ++j) {
            double mean = s[j] * invB;
            double var  = s[4 + j] * invB - mean * mean;
            float sv = __ldg(&gamma[j]) * rsqrtf((float)var + 1e-5f);
            scv[j] = sv;
            shv[j] = __ldg(&beta[j]) - (float)mean * sv;
        }
        sbn[0] = make_float4(scv[0], scv[1], scv[2], scv[3]);
        sbn[1] = make_float4(shv[0], shv[1], shv[2], shv[3]);
    }
    __syncthreads();
    float4 sc = sbn[0], sh = sbn[1];
    #pragma unroll
    for (int q = 0; q < SPT; ++q) {
        size_t s = gtid + (size_t)q * STRIDE;
        if (s < (size_t)B) {
            float4 v = out[s];              // own write, L2-resident
            v.x = fmaf(v.x, sc.x, sh.x);
            v.y = fmaf(v.y, sc.y, sh.y);
            v.z = fmaf(v.z, sc.z, sh.z);
            v.w = fmaf(v.w, sc.w, sh.w);
            out[s] = v;
        }
    }
}

// ---------------------------------------------------------------------------
extern "C" void kernel_launch(void* const* d_in, const int* in_sizes, int n_in,
                              void* d_out, int out_size) {
    const float* x     = (const float*)d_in[0];   // [B,16]
    const float* w     = (const float*)d_in[1];   // [3,4,2]
    const float* fcw   = (const float*)d_in[2];   // [4,4]
    const float* fcb   = (const float*)d_in[3];   // [4]
    const float* gamma = (const float*)d_in[4];   // [4]
    const float* beta  = (const float*)d_in[5];   // [4]
    int B = in_sizes[0] / 16;
    float* out = (float*)d_out;

    k_precompute<<<1, 128>>>(w, fcw, fcb);

    void* gcp = nullptr;
    cudaGetSymbolAddress(&gcp, g_Cb);
    cudaMemcpyToSymbolAsync(c_Cb, gcp, 108 * sizeof(u64), 0,
                            cudaMemcpyDeviceToDevice);

    k_fused<<<NBLK, NTHR>>>((const float4*)x, (float4*)out, B, gamma, beta);
}

// round 17
// speedup vs baseline: 1.2583x; 1.2583x over previous
#include <cuda_runtime.h>

// ============================================================================
// QFCModel: 4-qubit / 3-layer variational circuit + Linear(4,4) + BatchNorm1d
//
//   out_j(sample) = sum_{k in {0,1,2}^4} C_j[k] * prod_i b_i[k_i],
//   b_i = (1, cos t_i, sin t_i),  t_i = 2*pi*(x_i - mn)*inv_range
//
// R16 = revert to R6's best-measured fused structure (shared-memory sample
// tile: x read from gmem ONCE, outputs written ONCE; coefficients via
// __constant__/LDC; single-pair f32x2 contraction) with one change:
// NBLK 256 -> 296 (= 2 x 148; 117 regs -> 2 blocks/SM capacity everywhere,
// all 296 resident -> spin barriers safe; R6 idled ~24 block-slots).
// 3-node graph: precompute(1 blk) -> memcpyToSymbol -> fused persistent.
// ============================================================================

typedef unsigned long long u64;

#define NBLK 296
#define NTHR 256
#define SPT  8          // 296*256*8 = 606208 >= 524288 (guards handle tail)

static __constant__ u64 c_C2[324];     // [4][81] lane-duplicated coeffs

__device__ u64      g_C2[324];
__device__ unsigned g_umin = 0xFFFFFFFFu;
__device__ unsigned g_umax = 0u;
__device__ unsigned g_bar0 = 0u, g_bar1 = 0u;
__device__ double   g_accd[8] = {0,0,0,0,0,0,0,0};   // sum[4], sumsq[4]

__device__ __forceinline__ u64 pk2(float lo, float hi) {
    u64 r; asm("mov.b64 %0, {%1, %2};" : "=l"(r) : "f"(lo), "f"(hi)); return r;
}
__device__ __forceinline__ void upk2(float& lo, float& hi, u64 v) {
    asm("mov.b64 {%0, %1}, %2;" : "=f"(lo), "=f"(hi) : "l"(v));
}
__device__ __forceinline__ u64 fma2(u64 a, u64 b, u64 c) {
    u64 d; asm("fma.rn.f32x2 %0, %1, %2, %3;" : "=l"(d) : "l"(a), "l"(b), "l"(c));
    return d;
}
// order-preserving float <-> uint (for integer atomic min/max)
__device__ __forceinline__ unsigned fenc(float f) {
    unsigned u = __float_as_uint(f);
    return (u & 0x80000000u) ? ~u : (u | 0x80000000u);
}
__device__ __forceinline__ float fdec(unsigned u) {
    return (u & 0x80000000u) ? __uint_as_float(u & 0x7FFFFFFFu)
                             : __uint_as_float(~u);
}
// software grid barrier: atomic arrive; ld.cg poll with bounded fallback
__device__ __forceinline__ void grid_barrier(unsigned* ctr) {
    __syncthreads();
    if (threadIdx.x == 0) {
        __threadfence();
        unsigned arrived = atomicAdd(ctr, 1u) + 1u;
        if (arrived < gridDim.x) {
            int spins = 0;
            for (;;) {
                unsigned v;
                asm volatile("ld.global.cg.u32 %0, [%1];" : "=r"(v) : "l"(ctr));
                if (v >= gridDim.x) break;
                if (++spins >= 1024) {      // fallback: force L2 read
                    if (atomicAdd(ctr, 0u) >= gridDim.x) break;
                    spins = 0;
                }
                __nanosleep(32);
            }
        }
        __threadfence();
    }
    __syncthreads();
}

// ---------------------------------------------------------------------------
// Node 1 (1 block, 128 threads): probe-grid coefficient construction + reset
// of all per-replay device state. Thread t < 81 simulates the circuit at
// probe point with base-3 digits of t (wire 0 most significant, stride 27),
// t_i = {0, pi/2, pi}[digit]. Amplitude bit (3-i) = wire i.
// ---------------------------------------------------------------------------
__global__ void __launch_bounds__(128) k_precompute(const float* __restrict__ w,
                                                    const float* __restrict__ fcw,
                                                    const float* __restrict__ fcb) {
    __shared__ float E[4][81];
    __shared__ float F[4][81];
    __shared__ float tc[24], ts[24];
    __shared__ float sfw[16], sfb[4];

    int t = threadIdx.x;
    if (t == 127) {            // per-replay resets (run before the fused kernel)
        g_umin = 0xFFFFFFFFu;
        g_umax = 0u;
        g_bar0 = 0u;
        g_bar1 = 0u;
        #pragma unroll
        for (int j = 0; j < 8; ++j) g_accd[j] = 0.0;
    }
    if (t < 24) { float a = 0.5f * w[t]; tc[t] = cosf(a); ts[t] = sinf(a); }
    if (t < 16) sfw[t] = fcw[t];
    if (t < 4)  sfb[t] = fcb[t];
    __syncthreads();

    if (t < 81) {
        int gd[4];
        gd[0] = t / 27; gd[1] = (t / 9) % 3; gd[2] = (t / 3) % 3; gd[3] = t % 3;
        const float encc[3] = {1.0f, 0.70710678118654752f, 0.0f};
        const float encs[3] = {0.0f, 0.70710678118654752f, 1.0f};

        float ar[16], ai[16];
        #pragma unroll
        for (int a = 0; a < 16; ++a) { ar[a] = 0.0f; ai[a] = 0.0f; }
        ar[0] = 1.0f;

        // input-encoding RYs
        #pragma unroll
        for (int i = 0; i < 4; ++i) {
            int m = 8 >> i;
            float c = encc[gd[i]], s = encs[gd[i]];
            #pragma unroll
            for (int a = 0; a < 16; ++a) {
                if (a & m) continue;
                float x0r = ar[a],     x0i = ai[a];
                float x1r = ar[a | m], x1i = ai[a | m];
                ar[a]     = c * x0r - s * x1r;  ai[a]     = c * x0i - s * x1i;
                ar[a | m] = s * x0r + c * x1r;  ai[a | m] = s * x0i + c * x1i;
            }
        }
        // ansatz layers
        for (int l = 0; l < 3; ++l) {
            #pragma unroll
            for (int i = 0; i < 4; ++i) {
                int m = 8 >> i;
                int base = (l * 4 + i) * 2;
                float cy = tc[base], sy = ts[base];
                float cz = tc[base + 1], sz = ts[base + 1];
                #pragma unroll
                for (int a = 0; a < 16; ++a) {
                    if (a & m) continue;
                    float x0r = ar[a],     x0i = ai[a];
                    float x1r = ar[a | m], x1i = ai[a | m];
                    float n0r = cy * x0r - sy * x1r, n0i = cy * x0i - sy * x1i;
                    float n1r = sy * x0r + cy * x1r, n1i = sy * x0i + cy * x1i;
                    // RZ: bit0 phase (cz - i sz), bit1 phase (cz + i sz)
                    ar[a]     = cz * n0r + sz * n0i;  ai[a]     = cz * n0i - sz * n0r;
                    ar[a | m] = cz * n1r - sz * n1i;  ai[a | m] = cz * n1i + sz * n1r;
                }
            }
            // CNOT chain (0,1)(1,2)(2,3)(3,0)
            #pragma unroll
            for (int e = 0; e < 4; ++e) {
                int cwire = e, twire = (e + 1) & 3;
                int mc = 8 >> cwire, mt = 8 >> twire;
                #pragma unroll
                for (int a = 0; a < 16; ++a) {
                    if ((a & mc) && !(a & mt)) {
                        int b = a ^ mt;
                        float vr = ar[a], vi = ai[a];
                        ar[a] = ar[b]; ai[a] = ai[b];
                        ar[b] = vr;    ai[b] = vi;
                    }
                }
            }
        }
        // PauliZ expvals
        float z[4] = {0.f, 0.f, 0.f, 0.f};
        #pragma unroll
        for (int a = 0; a < 16; ++a) {
            float p = ar[a] * ar[a] + ai[a] * ai[a];
            #pragma unroll
            for (int i = 0; i < 4; ++i)
                z[i] += (a & (8 >> i)) ? -p : p;
        }
        #pragma unroll
        for (int j = 0; j < 4; ++j) {
            float o = sfb[j];
            #pragma unroll
            for (int i = 0; i < 4; ++i) o += sfw[j * 4 + i] * z[i];
            E[j][t] = o;
        }
    }
    __syncthreads();

    // Per-mode inverse transforms: f(0),f(pi/2),f(pi) -> (1,cos,sin) coeffs
    {
        float (*S)[81] = E; float (*D)[81] = F;
        const int strides[4] = {27, 9, 3, 1};
        #pragma unroll
        for (int mode = 0; mode < 4; ++mode) {
            int st = strides[mode];
            for (int idx = t; idx < 324; idx += 128) {
                int j = idx / 81, g = idx - (idx / 81) * 81;
                int dg = (g / st) % 3;
                if (dg == 0) {
                    float f0 = S[j][g], f1 = S[j][g + st], f2 = S[j][g + 2 * st];
                    float A = 0.5f * (f0 + f2);
                    D[j][g]          = A;                 // const
                    D[j][g + st]     = 0.5f * (f0 - f2);  // cos coeff
                    D[j][g + 2 * st] = f1 - A;            // sin coeff
                }
            }
            __syncthreads();
            float (*tmp)[81] = S; S = D; D = tmp;
        }
        // after 4 swaps result is back in E; write lane-duplicated packed
        for (int idx = t; idx < 324; idx += 128) {
            float v = E[idx / 81][idx - (idx / 81) * 81];
            g_C2[idx] = pk2(v, v);
        }
    }
}

// ---------------------------------------------------------------------------
// Node 3: persistent fused kernel (R6 structure).
//   Phase 1: load 8 samples/thread into smem tile, min/max -> global atomics
//   barrier -> Phase 2: contraction (4 f32x2 pairs, coeffs via LDC), outputs
//   overwrite x in smem, BN stats -> RED.F64 -> barrier -> Phase 3: BN apply
//   + single store to gmem.
// ---------------------------------------------------------------------------
__global__ void __launch_bounds__(NTHR, 2) k_fused(const float4* __restrict__ x4,
                                                   float4* __restrict__ out, int B,
                                                   const float* __restrict__ gamma,
                                                   const float* __restrict__ beta) {
    __shared__ float4 sx[SPT][NTHR];        // 32KB tile: x, then outputs
    __shared__ unsigned srmn[8], srmx[8];
    __shared__ float red[8][8];
    __shared__ float4 sbn[2];               // [0]=scale, [1]=shift

    int tid = threadIdx.x;
    size_t base = (size_t)blockIdx.x * (NTHR * SPT);

    // ---- Phase 1: load + min/max ----
    float mn = 3.402823e38f, mx = -3.402823e38f;
    #pragma unroll
    for (int q = 0; q < SPT; ++q) {
        size_t s = base + tid + (size_t)q * NTHR;
        float4 v = make_float4(0.f, 0.f, 0.f, 0.f);
        if (s < (size_t)B) {
            v = __ldg(x4 + s * 4);          // row stride = 16 floats
            mn = fminf(mn, fminf(fminf(v.x, v.y), fminf(v.z, v.w)));
            mx = fmaxf(mx, fmaxf(fmaxf(v.x, v.y), fmaxf(v.z, v.w)));
        }
        sx[q][tid] = v;
    }
    unsigned emn = __reduce_min_sync(0xffffffffu, fenc(mn));
    unsigned emx = __reduce_max_sync(0xffffffffu, fenc(mx));
    int w = tid >> 5;
    if ((tid & 31) == 0) { srmn[w] = emn; srmx[w] = emx; }
    __syncthreads();
    if (tid == 0) {
        unsigned a = srmn[0], b = srmx[0];
        #pragma unroll
        for (int i = 1; i < 8; ++i) { a = min(a, srmn[i]); b = max(b, srmx[i]); }
        atomicMin(&g_umin, a);
        atomicMax(&g_umax, b);
    }

    grid_barrier(&g_bar0);

    // ---- Phase 2: contraction + BN stats ----
    unsigned uamn, uamx;
    asm volatile("ld.global.cg.u32 %0, [%1];" : "=r"(uamn) : "l"(&g_umin));
    asm volatile("ld.global.cg.u32 %0, [%1];" : "=r"(uamx) : "l"(&g_umax));
    float mnv = fdec(uamn);
    float scl = 6.283185307179586f / (fdec(uamx) - mnv + 1e-8f);

    float p[8];
    #pragma unroll
    for (int j = 0; j < 8; ++j) p[j] = 0.f;

    #pragma unroll
    for (int pr = 0; pr < SPT / 2; ++pr) {
        size_t s0 = base + tid + (size_t)pr * NTHR;
        size_t s1 = s0 + (size_t)(SPT / 2) * NTHR;
        float4 va = sx[pr][tid];
        float4 vb = sx[pr + SPT / 2][tid];

        float sa0, ca0, sa1, ca1, sa2, ca2, sa3, ca3;
        float sb0, cb0, sb1, cb1, sb2, cb2, sb3, cb3;
        __sincosf((va.x - mnv) * scl, &sa0, &ca0);
        __sincosf((va.y - mnv) * scl, &sa1, &ca1);
        __sincosf((va.z - mnv) * scl, &sa2, &ca2);
        __sincosf((va.w - mnv) * scl, &sa3, &ca3);
        __sincosf((vb.x - mnv) * scl, &sb0, &cb0);
        __sincosf((vb.y - mnv) * scl, &sb1, &cb1);
        __sincosf((vb.z - mnv) * scl, &sb2, &cb2);
        __sincosf((vb.w - mnv) * scl, &sb3, &cb3);

        u64 C0 = pk2(ca0, cb0), S0 = pk2(sa0, sb0);
        u64 C1 = pk2(ca1, cb1), S1 = pk2(sa1, sb1);
        u64 C2 = pk2(ca2, cb2), S2 = pk2(sa2, sb2);
        u64 C3 = pk2(ca3, cb3), S3 = pk2(sa3, sb3);

        u64 o[4];
        #pragma unroll
        for (int j = 0; j < 4; ++j) {
            const u64* C = &c_C2[j * 81];
            u64 r1[27];
            #pragma unroll
            for (int k = 0; k < 27; ++k)
                r1[k] = fma2(C0, C[27 + k], fma2(S0, C[54 + k], C[k]));
            u64 r2[9];
            #pragma unroll
            for (int k = 0; k < 9; ++k)
                r2[k] = fma2(C1, r1[9 + k], fma2(S1, r1[18 + k], r1[k]));
            u64 r3[3];
            #pragma unroll
            for (int k = 0; k < 3; ++k)
                r3[k] = fma2(C2, r2[3 + k], fma2(S2, r2[6 + k], r2[k]));
            o[j] = fma2(C3, r3[1], fma2(S3, r3[2], r3[0]));
        }

        float oa[4], ob[4];
        #pragma unroll
        for (int j = 0; j < 4; ++j) upk2(oa[j], ob[j], o[j]);

        // outputs overwrite x tile in place
        sx[pr][tid]           = make_float4(oa[0], oa[1], oa[2], oa[3]);
        sx[pr + SPT / 2][tid] = make_float4(ob[0], ob[1], ob[2], ob[3]);

        #pragma unroll
        for (int j = 0; j < 4; ++j) {
            float xa = (s0 < (size_t)B) ? oa[j] : 0.f;
            float xb = (s1 < (size_t)B) ? ob[j] : 0.f;
            p[j]     += xa + xb;
            p[4 + j] += xa * xa + xb * xb;
        }
    }

    #pragma unroll
    for (int o2 = 16; o2 > 0; o2 >>= 1) {
        #pragma unroll
        for (int j = 0; j < 8; ++j)
            p[j] += __shfl_xor_sync(0xffffffffu, p[j], o2);
    }
    if ((tid & 31) == 0) {
        #pragma unroll
        for (int j = 0; j < 8; ++j) red[w][j] = p[j];
    }
    __syncthreads();
    if (tid < 8) {
        float a = 0.f;
        #pragma unroll
        for (int i = 0; i < 8; ++i) a += red[i][tid];
        atomicAdd(&g_accd[tid], (double)a);
    }

    grid_barrier(&g_bar1);

    // ---- Phase 3: BN params + apply + single store ----
    if (tid == 0) {
        double s[8];
        #pragma unroll
        for (int j = 0; j < 8; ++j) {
            double v;
            asm volatile("ld.global.cg.f64 %0, [%1];" : "=d"(v) : "l"(&g_accd[j]));
            s[j] = v;
        }
        double invB = 1.0 / (double)B;
        float scv[4], shv[4];
        #pragma unroll
        for (int j = 0; j < 4; ++j) {
            double mean = s[j] * invB;
            double var  = s[4 + j] * invB - mean * mean;
            float sv = __ldg(&gamma[j]) * rsqrtf((float)var + 1e-5f);
            scv[j] = sv;
            shv[j] = __ldg(&beta[j]) - (float)mean * sv;
        }
        sbn[0] = make_float4(scv[0], scv[1], scv[2], scv[3]);
        sbn[1] = make_float4(shv[0], shv[1], shv[2], shv[3]);
    }
    __syncthreads();
    float4 sc = sbn[0], sh = sbn[1];
    #pragma unroll
    for (int q = 0; q < SPT; ++q) {
        size_t s = base + tid + (size_t)q * NTHR;
        if (s < (size_t)B) {
            float4 v = sx[q][tid];
            v.x = fmaf(v.x, sc.x, sh.x);
            v.y = fmaf(v.y, sc.y, sh.y);
            v.z = fmaf(v.z, sc.z, sh.z);
            v.w = fmaf(v.w, sc.w, sh.w);
            out[s] = v;
        }
    }
}

// ---------------------------------------------------------------------------
extern "C" void kernel_launch(void* const* d_in, const int* in_sizes, int n_in,
                              void* d_out, int out_size) {
    const float* x     = (const float*)d_in[0];   // [B,16]
    const float* w     = (const float*)d_in[1];   // [3,4,2]
    const float* fcw   = (const float*)d_in[2];   // [4,4]
    const float* fcb   = (const float*)d_in[3];   // [4]
    const float* gamma = (const float*)d_in[4];   // [4]
    const float* beta  = (const float*)d_in[5];   // [4]
    int B = in_sizes[0] / 16;
    float* out = (float*)d_out;

    k_precompute<<<1, 128>>>(w, fcw, fcb);

    void* gcp = nullptr;
    cudaGetSymbolAddress(&gcp, g_C2);
    cudaMemcpyToSymbolAsync(c_C2, gcp, 324 * sizeof(u64), 0,
                            cudaMemcpyDeviceToDevice);

    k_fused<<<NBLK, NTHR>>>((const float4*)x, (float4*)out, B, gamma, beta);
}